// round 10
// baseline (speedup 1.0000x reference)
#include <cuda_runtime.h>

// 3-level Haar DWT, fully fused.
// x: [B, L=16384] fp32. Output concat: [cA3 (B*2048) | cD3 (B*2048) | cD2 (B*4096) | cD1 (B*8192)]
//
// One thread handles 8 consecutive input samples (one cA3/cD3 group):
//   cD1[4k..4k+3], cD2[2k..2k+1], cD3[k], cA3[k]
// All loads are 2x float4, all stores vectorized & coalesced. No smem, no sync.

__global__ __launch_bounds__(256) void haar3_kernel(
    const float4* __restrict__ in4,   // input viewed as float4
    float*  __restrict__ cA3,         // B*2048
    float*  __restrict__ cD3,         // B*2048
    float2* __restrict__ cD2_2,       // B*4096 floats = B*2048 float2
    float4* __restrict__ cD1_4,       // B*8192 floats = B*2048 float4
    int total_groups)                 // B * 2048
{
    int t = blockIdx.x * blockDim.x + threadIdx.x;
    if (t >= total_groups) return;

    // t = row*2048 + k ; input float4 base = row*4096 + 2k = 2*t
    float4 v0 = in4[2 * t];
    float4 v1 = in4[2 * t + 1];

    const float S  = 0.70710678118654752440f;   // sqrt(1/2)
    const float S2 = 0.5f;                      // S^2
    const float S3 = 0.35355339059327376220f;   // S^3

    // level 1 pair sums/diffs
    float a0 = v0.x + v0.y, d0 = v0.x - v0.y;
    float a1 = v0.z + v0.w, d1 = v0.z - v0.w;
    float a2 = v1.x + v1.y, d2 = v1.x - v1.y;
    float a3 = v1.z + v1.w, d3 = v1.z - v1.w;

    // level 2
    float A0 = a0 + a1, D0 = a0 - a1;
    float A1 = a2 + a3, D1 = a2 - a3;

    // level 3
    float ca3 = S3 * (A0 + A1);
    float cd3 = S3 * (A0 - A1);

    // stores — all coalesced by construction
    cD1_4[t] = make_float4(S * d0, S * d1, S * d2, S * d3);
    cD2_2[t] = make_float2(S2 * D0, S2 * D1);
    cD3[t]   = cd3;
    cA3[t]   = ca3;
}

extern "C" void kernel_launch(void* const* d_in, const int* in_sizes, int n_in,
                              void* d_out, int out_size)
{
    const float* x = (const float*)d_in[0];
    float* out = (float*)d_out;

    const int L = 16384;
    const int B = in_sizes[0] / L;          // 2048
    const int total_groups = B * (L / 8);   // B * 2048

    // Output layout: [cA3 | cD3 | cD2 | cD1]
    float*  cA3  = out;
    float*  cD3  = out + (size_t)B * (L / 8);                 // + B*2048
    float2* cD2  = (float2*)(out + (size_t)2 * B * (L / 8));  // + B*4096 floats
    float4* cD1  = (float4*)(out + (size_t)B * (L / 2));      // + B*8192 floats

    int threads = 256;
    int blocks = (total_groups + threads - 1) / threads;
    haar3_kernel<<<blocks, threads>>>((const float4*)x, cA3, cD3, cD2, cD1, total_groups);
}